// round 5
// baseline (speedup 1.0000x reference)
#include <cuda_runtime.h>

// out[m,o] = sum_c |x[m,c] - w[c,o]| + b[o]
//          = 2*sum_c max(x[m,c], w[c,o]) - Sx[m] - Sw[o] + b[o]
// 4(m) x 8(o) thread tile, o split as [o0, o0+3] U [o0+32, o0+35]:
// every LDS.128 is 16B-lane-stride -> conflict-free -> 12 wavefronts / 32 MACs.

constexpr int C    = 64;    // channels (reduction dim)
constexpr int OUTC = 128;   // output channels
constexpr int BM   = 64;    // rows per block
constexpr int BO   = 64;    // output cols per block
constexpr int XS   = 68;    // padded stride for transposed x tile

__global__ __launch_bounds__(128, 6)
void lp1_maxtrick_kernel(const float* __restrict__ x,
                         const float* __restrict__ w,
                         const float* __restrict__ b,
                         float* __restrict__ out)
{
    __shared__ float w_s[C * BO];   // [c][o]  16 KB
    __shared__ float x_s[C * XS];   // [c][m]  17.4 KB (transposed, padded)
    __shared__ float sx_s[BM];
    __shared__ float beta_s[BO];

    const int tid   = threadIdx.x;
    const int m_blk = blockIdx.x * BM;
    const int o_blk = blockIdx.y * BO;

    // ---- stage w slice [C][BO]: 1024 float4, 8 per thread (coalesced) ----
    #pragma unroll
    for (int i = 0; i < 8; ++i) {
        int idx = tid + 128 * i;            // 0..1023
        int c   = idx >> 4;                 // 16 float4 per c-row
        int o4  = idx & 15;
        float4 v = *(const float4*)(w + c * OUTC + o_blk + o4 * 4);
        *(float4*)(&w_s[c * BO + o4 * 4]) = v;
    }

    // ---- stage x tile transposed: 1024 float4, 8 per thread ----
    #pragma unroll
    for (int i = 0; i < 8; ++i) {
        int idx = tid + 128 * i;
        int m   = idx >> 4;                 // 16 float4 per row (C=64)
        int c   = (idx & 15) << 2;
        float4 v = *(const float4*)(x + (size_t)(m_blk + m) * C + c);
        x_s[(c + 0) * XS + m] = v.x;
        x_s[(c + 1) * XS + m] = v.y;
        x_s[(c + 2) * XS + m] = v.z;
        x_s[(c + 3) * XS + m] = v.w;
    }
    __syncthreads();

    // ---- prologue: beta[o] = b[o] - Sw[o]; sx[m] = sum_c x ----
    if (tid < BO) {
        float s = 0.f;
        #pragma unroll
        for (int c = 0; c < C; ++c) s += w_s[c * BO + tid];
        beta_s[tid] = b[o_blk + tid] - s;
    } else {
        int m = tid - BO;                   // 64..127 -> m 0..63
        float s = 0.f;
        #pragma unroll
        for (int c = 0; c < C; ++c) s += x_s[c * XS + m];
        sx_s[m] = s;
    }
    __syncthreads();

    // ---- main loop: 4(m) x 8(o) register tile, conflict-free LDS ----
    const int o0 = (tid & 7) * 4;    // 8 o-groups; pair load at o0+32
    const int m0 = (tid >> 3) * 4;   // 16 m-groups covering 64

    float acc[4][8];
    #pragma unroll
    for (int i = 0; i < 4; ++i)
        #pragma unroll
        for (int j = 0; j < 8; ++j) acc[i][j] = 0.f;

    const float* xp = &x_s[m0];
    const float* wp = &w_s[o0];

    #pragma unroll 8
    for (int c = 0; c < C; ++c) {
        float4 xv  = *(const float4*)(xp + c * XS);
        float4 wv0 = *(const float4*)(wp + c * BO);        // lanes: 16B stride
        float4 wv1 = *(const float4*)(wp + c * BO + 32);   // lanes: 16B stride
        float xa[4] = {xv.x, xv.y, xv.z, xv.w};
        float wa[8] = {wv0.x, wv0.y, wv0.z, wv0.w,
                       wv1.x, wv1.y, wv1.z, wv1.w};
        #pragma unroll
        for (int i = 0; i < 4; ++i)
            #pragma unroll
            for (int j = 0; j < 8; ++j)
                acc[i][j] += fmaxf(xa[i], wa[j]);   // FMNMX (alu) + FADD (fma)
    }

    // ---- epilogue: out = 2*acc - sx + beta ----
    float bet[8];
    #pragma unroll
    for (int j = 0; j < 4; ++j) bet[j] = beta_s[o0 + j];
    #pragma unroll
    for (int j = 0; j < 4; ++j) bet[4 + j] = beta_s[o0 + 32 + j];

    #pragma unroll
    for (int i = 0; i < 4; ++i) {
        float base = -sx_s[m0 + i];
        float* op = out + (size_t)(m_blk + m0 + i) * OUTC + o_blk;
        float4 r0, r1;
        r0.x = fmaf(2.f, acc[i][0], base + bet[0]);
        r0.y = fmaf(2.f, acc[i][1], base + bet[1]);
        r0.z = fmaf(2.f, acc[i][2], base + bet[2]);
        r0.w = fmaf(2.f, acc[i][3], base + bet[3]);
        r1.x = fmaf(2.f, acc[i][4], base + bet[4]);
        r1.y = fmaf(2.f, acc[i][5], base + bet[5]);
        r1.z = fmaf(2.f, acc[i][6], base + bet[6]);
        r1.w = fmaf(2.f, acc[i][7], base + bet[7]);
        *(float4*)(op + o0)      = r0;
        *(float4*)(op + o0 + 32) = r1;
    }
}

extern "C" void kernel_launch(void* const* d_in, const int* in_sizes, int n_in,
                              void* d_out, int out_size)
{
    const float* x = (const float*)d_in[0];   // [M, 64]
    const float* w = (const float*)d_in[1];   // [64, 128]
    const float* b = (const float*)d_in[2];   // [128]
    float* out = (float*)d_out;               // [M, 128]

    int M = in_sizes[0] / C;                  // 25088
    dim3 grid(M / BM, OUTC / BO);             // (392, 2) = 784 blocks
    lp1_maxtrick_kernel<<<grid, 128>>>(x, w, b, out);
}

// round 6
// speedup vs baseline: 1.4855x; 1.4855x over previous
#include <cuda_runtime.h>

// out[m,o] = sum_c |x[m,c] - w[c,o]| + b[o]
//          = 2*sum_c max(x[m,c], w[c,o]) - Sx[m] - Sw[o] + b[o]
// R1 shape (proven best): 256 thr, 64x64 tile, 4x4/thread, conflict-free LDS.128.
// Changes vs R1: no manual prefetch (fewer regs/MOVs), reg cap for 6 blocks/SM
// -> single wave (784 <= 888) and 48 warps/SM to hide LDS latency.

constexpr int C    = 64;    // channels (reduction dim)
constexpr int OUTC = 128;   // output channels
constexpr int BM   = 64;    // rows per block
constexpr int BO   = 64;    // output cols per block
constexpr int XS   = 68;    // padded stride for transposed x tile

__global__ __launch_bounds__(256, 6)
void lp1_maxtrick_kernel(const float* __restrict__ x,
                         const float* __restrict__ w,
                         const float* __restrict__ b,
                         float* __restrict__ out)
{
    __shared__ float w_s[C * BO];   // [c][o]  16 KB
    __shared__ float x_s[C * XS];   // [c][m]  17.4 KB (transposed, padded)
    __shared__ float sx_s[BM];
    __shared__ float beta_s[BO];

    const int tid   = threadIdx.x;
    const int m_blk = blockIdx.x * BM;
    const int o_blk = blockIdx.y * BO;

    // ---- stage w slice [C][BO]: 1024 float4 (coalesced) ----
    #pragma unroll
    for (int i = 0; i < 4; ++i) {
        int idx = tid + 256 * i;
        int c   = idx >> 4;                 // 16 float4 per c-row
        int o4  = idx & 15;
        float4 v = *(const float4*)(w + c * OUTC + o_blk + o4 * 4);
        *(float4*)(&w_s[c * BO + o4 * 4]) = v;
    }

    // ---- stage x tile transposed: 1024 float4 ----
    #pragma unroll
    for (int i = 0; i < 4; ++i) {
        int idx = tid + 256 * i;
        int m   = idx >> 4;                 // 16 float4 per row (C=64)
        int c   = (idx & 15) << 2;
        float4 v = *(const float4*)(x + (size_t)(m_blk + m) * C + c);
        x_s[(c + 0) * XS + m] = v.x;
        x_s[(c + 1) * XS + m] = v.y;
        x_s[(c + 2) * XS + m] = v.z;
        x_s[(c + 3) * XS + m] = v.w;
    }
    __syncthreads();

    // ---- prologue: beta[o] = b[o] - Sw[o]; sx[m] = sum_c x ----
    if (tid < BO) {
        float s = 0.f;
        #pragma unroll
        for (int c = 0; c < C; ++c) s += w_s[c * BO + tid];
        beta_s[tid] = b[o_blk + tid] - s;
    } else if (tid < BO + BM) {
        int m = tid - BO;
        float s = 0.f;
        #pragma unroll
        for (int c = 0; c < C; ++c) s += x_s[c * XS + m];
        sx_s[m] = s;
    }
    __syncthreads();

    // ---- main loop: 4x4 register tile, conflict-free LDS.128 ----
    const int o0 = (tid & 15) * 4;   // 16 o-groups, 16B lane stride
    const int m0 = (tid >> 4) * 4;   // 16 m-groups, 16B lane stride

    float acc[4][4];
    #pragma unroll
    for (int i = 0; i < 4; ++i)
        #pragma unroll
        for (int j = 0; j < 4; ++j) acc[i][j] = 0.f;

    #pragma unroll 16
    for (int c = 0; c < C; ++c) {
        float4 xv = *(const float4*)(&x_s[c * XS + m0]);
        float4 wv = *(const float4*)(&w_s[c * BO + o0]);
        #pragma unroll
        for (int i = 0; i < 4; ++i) {
            float xi = (i == 0) ? xv.x : (i == 1) ? xv.y : (i == 2) ? xv.z : xv.w;
            acc[i][0] += fmaxf(xi, wv.x);   // FMNMX (alu) + FADD (fma)
            acc[i][1] += fmaxf(xi, wv.y);
            acc[i][2] += fmaxf(xi, wv.z);
            acc[i][3] += fmaxf(xi, wv.w);
        }
    }

    // ---- epilogue: out = 2*acc - sx + beta ----
    float bet[4];
    #pragma unroll
    for (int j = 0; j < 4; ++j) bet[j] = beta_s[o0 + j];

    #pragma unroll
    for (int i = 0; i < 4; ++i) {
        float base = -sx_s[m0 + i];
        float4 r;
        r.x = fmaf(2.f, acc[i][0], base + bet[0]);
        r.y = fmaf(2.f, acc[i][1], base + bet[1]);
        r.z = fmaf(2.f, acc[i][2], base + bet[2]);
        r.w = fmaf(2.f, acc[i][3], base + bet[3]);
        *(float4*)(out + (size_t)(m_blk + m0 + i) * OUTC + o_blk + o0) = r;
    }
}

extern "C" void kernel_launch(void* const* d_in, const int* in_sizes, int n_in,
                              void* d_out, int out_size)
{
    const float* x = (const float*)d_in[0];   // [M, 64]
    const float* w = (const float*)d_in[1];   // [64, 128]
    const float* b = (const float*)d_in[2];   // [128]
    float* out = (float*)d_out;               // [M, 128]

    int M = in_sizes[0] / C;                  // 25088
    dim3 grid(M / BM, OUTC / BO);             // (392, 2) = 784 blocks
    lp1_maxtrick_kernel<<<grid, 256>>>(x, w, b, out);
}

// round 7
// speedup vs baseline: 1.5006x; 1.0102x over previous
#include <cuda_runtime.h>

// out[m,o] = sum_c |x[m,c] - w[c,o]| + b[o]
//          = 2*sum_c max(x[m,c], w[c,o]) - Sx[m] - Sw[o] + b[o]
// R1 compute shape (256 thr, 64x64 block tile, 4x4/thread, conflict-free LDS.128)
// + in-block split-K (two c-passes of 32) -> smem 34KB -> 17.2KB so ~6-7 blocks/SM
// stay resident instead of the measured 4. Accumulation order identical to R6.

constexpr int C    = 64;    // channels (reduction dim)
constexpr int CP   = 32;    // channels per pass
constexpr int OUTC = 128;   // output channels
constexpr int BM   = 64;    // rows per block
constexpr int BO   = 64;    // output cols per block
constexpr int XS   = 68;    // padded stride for transposed x tile

__global__ __launch_bounds__(256, 6)
void lp1_maxtrick_kernel(const float* __restrict__ x,
                         const float* __restrict__ w,
                         const float* __restrict__ b,
                         float* __restrict__ out)
{
    __shared__ float w_s[CP * BO];   // [c][o]  8 KB
    __shared__ float x_s[CP * XS];   // [c][m]  8.7 KB (transposed, padded)
    __shared__ float sx_s[BM];
    __shared__ float beta_s[BO];

    const int tid   = threadIdx.x;
    const int m_blk = blockIdx.x * BM;
    const int o_blk = blockIdx.y * BO;

    const int o0 = (tid & 15) * 4;   // 16 o-groups, 16B lane stride
    const int m0 = (tid >> 4) * 4;   // 16 m-groups, 16B lane stride

    float acc[4][4];
    #pragma unroll
    for (int i = 0; i < 4; ++i)
        #pragma unroll
        for (int j = 0; j < 4; ++j) acc[i][j] = 0.f;

    // per-thread partial sums for the epilogue corrections
    float beta_acc = (tid < BO) ? b[o_blk + tid] : 0.f;   // b[o] - Sw[o]
    float sx_acc   = 0.f;                                 // Sx[m]

    #pragma unroll
    for (int pass = 0; pass < 2; ++pass) {
        const int cbase = pass * CP;

        // ---- stage w half [CP][BO]: 512 float4 (coalesced) ----
        #pragma unroll
        for (int i = 0; i < 2; ++i) {
            int idx = tid + 256 * i;            // 0..511
            int c   = idx >> 4;                 // 16 float4 per c-row
            int o4  = idx & 15;
            float4 v = *(const float4*)(w + (cbase + c) * OUTC + o_blk + o4 * 4);
            *(float4*)(&w_s[c * BO + o4 * 4]) = v;
        }

        // ---- stage x half transposed: 512 float4 ----
        #pragma unroll
        for (int i = 0; i < 2; ++i) {
            int idx = tid + 256 * i;            // 0..511
            int m   = idx >> 3;                 // 8 float4 per row (CP=32)
            int c   = (idx & 7) << 2;
            float4 v = *(const float4*)(x + (size_t)(m_blk + m) * C + cbase + c);
            x_s[(c + 0) * XS + m] = v.x;
            x_s[(c + 1) * XS + m] = v.y;
            x_s[(c + 2) * XS + m] = v.z;
            x_s[(c + 3) * XS + m] = v.w;
        }
        __syncthreads();

        // ---- prologue partials for this half ----
        if (tid < BO) {
            #pragma unroll
            for (int c = 0; c < CP; ++c) beta_acc -= w_s[c * BO + tid];
        } else if (tid < BO + BM) {
            int m = tid - BO;
            #pragma unroll
            for (int c = 0; c < CP; ++c) sx_acc += x_s[c * XS + m];
        }

        // ---- main loop: 4x4 register tile, conflict-free LDS.128 ----
        #pragma unroll 16
        for (int c = 0; c < CP; ++c) {
            float4 xv = *(const float4*)(&x_s[c * XS + m0]);
            float4 wv = *(const float4*)(&w_s[c * BO + o0]);
            #pragma unroll
            for (int i = 0; i < 4; ++i) {
                float xi = (i == 0) ? xv.x : (i == 1) ? xv.y : (i == 2) ? xv.z : xv.w;
                acc[i][0] += fmaxf(xi, wv.x);   // FMNMX (alu) + FADD (fma)
                acc[i][1] += fmaxf(xi, wv.y);
                acc[i][2] += fmaxf(xi, wv.z);
                acc[i][3] += fmaxf(xi, wv.w);
            }
        }
        __syncthreads();   // protect restage of the next pass
    }

    // ---- publish corrections, then epilogue ----
    if (tid < BO)            beta_s[tid]      = beta_acc;
    else if (tid < BO + BM)  sx_s[tid - BO]   = sx_acc;
    __syncthreads();

    float bet[4];
    #pragma unroll
    for (int j = 0; j < 4; ++j) bet[j] = beta_s[o0 + j];

    #pragma unroll
    for (int i = 0; i < 4; ++i) {
        float base = -sx_s[m0 + i];
        float4 r;
        r.x = fmaf(2.f, acc[i][0], base + bet[0]);
        r.y = fmaf(2.f, acc[i][1], base + bet[1]);
        r.z = fmaf(2.f, acc[i][2], base + bet[2]);
        r.w = fmaf(2.f, acc[i][3], base + bet[3]);
        *(float4*)(out + (size_t)(m_blk + m0 + i) * OUTC + o_blk + o0) = r;
    }
}

extern "C" void kernel_launch(void* const* d_in, const int* in_sizes, int n_in,
                              void* d_out, int out_size)
{
    const float* x = (const float*)d_in[0];   // [M, 64]
    const float* w = (const float*)d_in[1];   // [64, 128]
    const float* b = (const float*)d_in[2];   // [128]
    float* out = (float*)d_out;               // [M, 128]

    int M = in_sizes[0] / C;                  // 25088
    dim3 grid(M / BM, OUTC / BO);             // (392, 2) = 784 blocks
    lp1_maxtrick_kernel<<<grid, 256>>>(x, w, b, out);
}

// round 8
// speedup vs baseline: 1.5878x; 1.0581x over previous
#include <cuda_runtime.h>
#include <cstring>

// out[m,o] = sum_c |x[m,c] - w[c,o]| + b[o]
//          = 2*sum_c max(x[m,c], w[c,o]) - Sx[m] - Sw[o] + b[o]
// Issue-slot optimized: 8(m) x 4(o) thread tile with WARP-UNIFORM x loads
// (broadcast LDS.128 = 1 dispatch slot vs 4), packed add.rn.f32x2 accumulate
// (pack done in PTX-visible code so ptxas can coalesce the register pair).

constexpr int C    = 64;    // channels (reduction dim)
constexpr int CP   = 32;    // channels per split-K pass
constexpr int OUTC = 128;   // output channels
constexpr int BM   = 64;    // rows per block
constexpr int XS   = 68;    // padded stride for transposed x tile

__device__ __forceinline__ void fadd2(unsigned long long& acc, float a, float b) {
    float2 t = make_float2(a, b);
    unsigned long long tv;
    memcpy(&tv, &t, 8);                         // PTX mov.b64 {a,b} -> coalescible
    asm("add.rn.f32x2 %0, %0, %1;" : "+l"(acc) : "l"(tv));
}

__global__ __launch_bounds__(256)
void lp1_maxtrick_kernel(const float* __restrict__ x,
                         const float* __restrict__ w,
                         const float* __restrict__ b,
                         float* __restrict__ out)
{
    __shared__ float w_s[CP * OUTC];  // [c][o]  16 KB per pass
    __shared__ float x_s[CP * XS];    // [c][m]  8.7 KB per pass (transposed)
    __shared__ float sx_s[BM];
    __shared__ float beta_s[OUTC];

    const int tid   = threadIdx.x;
    const int m_blk = blockIdx.x * BM;

    const int o0 = (tid & 31) * 4;    // 32 o-groups, 16B lane stride (distinct lanes)
    const int m0 = (tid >> 5) * 8;    // warp-uniform -> broadcast x loads

    unsigned long long acc[8][2];     // acc[i][k] = packed sums for o pair (2k,2k+1)
    #pragma unroll
    for (int i = 0; i < 8; ++i) { acc[i][0] = 0ull; acc[i][1] = 0ull; }

    float beta_acc = (tid < OUTC) ? b[tid] : 0.f;   // -> b[o] - Sw[o]
    float sx_acc   = 0.f;                           // -> Sx[m]

    #pragma unroll
    for (int pass = 0; pass < 2; ++pass) {
        const int cbase = pass * CP;

        // ---- stage w half [CP][OUTC]: 1024 float4 (coalesced copy) ----
        #pragma unroll
        for (int i = 0; i < 4; ++i) {
            int idx = tid + 256 * i;              // 0..1023
            int c   = idx >> 5;                   // 32 float4 per c-row
            int o4  = idx & 31;
            *(float4*)(&w_s[c * OUTC + o4 * 4]) =
                *(const float4*)(w + (cbase + c) * OUTC + o4 * 4);
        }

        // ---- stage x half transposed: 512 float4 ----
        #pragma unroll
        for (int i = 0; i < 2; ++i) {
            int idx = tid + 256 * i;              // 0..511
            int m   = idx >> 3;                   // 8 float4 per row (CP=32)
            int c   = (idx & 7) << 2;
            float4 v = *(const float4*)(x + (size_t)(m_blk + m) * C + cbase + c);
            x_s[(c + 0) * XS + m] = v.x;
            x_s[(c + 1) * XS + m] = v.y;
            x_s[(c + 2) * XS + m] = v.z;
            x_s[(c + 3) * XS + m] = v.w;
        }
        __syncthreads();

        // ---- prologue partials ----
        if (tid < OUTC) {
            #pragma unroll
            for (int c = 0; c < CP; ++c) beta_acc -= w_s[c * OUTC + tid];
        } else if (tid < OUTC + BM) {
            int m = tid - OUTC;
            #pragma unroll
            for (int c = 0; c < CP; ++c) sx_acc += x_s[c * XS + m];
        }

        // ---- main loop ----
        #pragma unroll 8
        for (int c = 0; c < CP; ++c) {
            float4 xv0 = *(const float4*)(&x_s[c * XS + m0]);       // broadcast
            float4 xv1 = *(const float4*)(&x_s[c * XS + m0 + 4]);   // broadcast
            float4 wv  = *(const float4*)(&w_s[c * OUTC + o0]);     // 16B stride
            float xa[8] = {xv0.x, xv0.y, xv0.z, xv0.w,
                           xv1.x, xv1.y, xv1.z, xv1.w};
            #pragma unroll
            for (int i = 0; i < 8; ++i) {
                fadd2(acc[i][0], fmaxf(xa[i], wv.x), fmaxf(xa[i], wv.y));
                fadd2(acc[i][1], fmaxf(xa[i], wv.z), fmaxf(xa[i], wv.w));
            }
        }
        __syncthreads();   // protect restage of next pass
    }

    // ---- publish corrections ----
    if (tid < OUTC)            beta_s[tid]    = beta_acc;
    else if (tid < OUTC + BM)  sx_s[tid - OUTC] = sx_acc;
    __syncthreads();

    // ---- epilogue: out = 2*acc - sx + beta ----
    float bet[4];
    #pragma unroll
    for (int j = 0; j < 4; ++j) bet[j] = beta_s[o0 + j];

    #pragma unroll
    for (int i = 0; i < 8; ++i) {
        float base = -sx_s[m0 + i];
        float2 p0, p1;
        memcpy(&p0, &acc[i][0], 8);
        memcpy(&p1, &acc[i][1], 8);
        float4 r;
        r.x = fmaf(2.f, p0.x, base + bet[0]);
        r.y = fmaf(2.f, p0.y, base + bet[1]);
        r.z = fmaf(2.f, p1.x, base + bet[2]);
        r.w = fmaf(2.f, p1.y, base + bet[3]);
        *(float4*)(out + (size_t)(m_blk + m0 + i) * OUTC + o0) = r;
    }
}

extern "C" void kernel_launch(void* const* d_in, const int* in_sizes, int n_in,
                              void* d_out, int out_size)
{
    const float* x = (const float*)d_in[0];   // [M, 64]
    const float* w = (const float*)d_in[1];   // [64, 128]
    const float* b = (const float*)d_in[2];   // [128]
    float* out = (float*)d_out;               // [M, 128]

    int M = in_sizes[0] / C;                  // 25088
    dim3 grid(M / BM, 1);                     // (392, 1)
    lp1_maxtrick_kernel<<<grid, 256>>>(x, w, b, out);
}